// round 1
// baseline (speedup 1.0000x reference)
#include <cuda_runtime.h>
#include <cstddef>

// Row-normalize block-diagonal graph.
// edge_weight: [K, N*N] fp32 with N = 1024. row[e] = e / N (block-diagonal,
// closed form) so degree of source node r is sum of the contiguous 1024-float
// row r of the flattened [K*N, N] matrix. Output = w * (deg>0 ? 1/deg : 0).
//
// One warp per row: 32 lanes x 8 float4 = 1024 floats, kept in registers
// between the reduce and the scaled store -> exactly one read + one write
// of the 128 MB tensor. The `row` index array (128 MB) is never read.

static constexpr int N_ATOM = 1024;           // floats per row
static constexpr int F4_PER_LANE = N_ATOM / (32 * 4);  // 8

__global__ __launch_bounds__(256) void rownorm_kernel(
    const float* __restrict__ w,
    float* __restrict__ out,
    int nrows)
{
    int gtid = blockIdx.x * blockDim.x + threadIdx.x;
    int warp = gtid >> 5;
    int lane = threadIdx.x & 31;
    if (warp >= nrows) return;

    const float4* __restrict__ src =
        reinterpret_cast<const float4*>(w + (size_t)warp * N_ATOM);

    float4 v[F4_PER_LANE];
    float s = 0.0f;
#pragma unroll
    for (int i = 0; i < F4_PER_LANE; i++) {
        v[i] = src[lane + i * 32];
        s += (v[i].x + v[i].y) + (v[i].z + v[i].w);
    }

    // Warp tree-reduce the row sum.
#pragma unroll
    for (int off = 16; off > 0; off >>= 1)
        s += __shfl_xor_sync(0xFFFFFFFFu, s, off);

    float inv = (s > 0.0f) ? (1.0f / s) : 0.0f;

    float4* __restrict__ dst =
        reinterpret_cast<float4*>(out + (size_t)warp * N_ATOM);
#pragma unroll
    for (int i = 0; i < F4_PER_LANE; i++) {
        float4 t = v[i];
        t.x *= inv; t.y *= inv; t.z *= inv; t.w *= inv;
        dst[lane + i * 32] = t;
    }
}

extern "C" void kernel_launch(void* const* d_in, const int* in_sizes, int n_in,
                              void* d_out, int out_size)
{
    const float* w = (const float*)d_in[0];   // edge_weight [K, N*N]
    // d_in[1] = row indices (unused: closed-form e/N), d_in[2] = num_atom
    float* out = (float*)d_out;

    int total = in_sizes[0];                  // K * N * N
    int nrows = total / N_ATOM;               // K * N

    int threads = 256;
    int warps_per_block = threads / 32;
    int blocks = (nrows + warps_per_block - 1) / warps_per_block;
    rownorm_kernel<<<blocks, threads>>>(w, out, nrows);
}

// round 2
// speedup vs baseline: 1.0094x; 1.0094x over previous
#include <cuda_runtime.h>
#include <cstddef>

// Row-normalize block-diagonal graph, two-pass-per-warp variant.
//
// edge_weight: [K, N*N] fp32, N=1024. row[e] = e/N closed-form, so degree of
// source node r = sum of contiguous 1024-float row r. Output = w * 1/deg.
//
// R1 learning: register-resident row cache (32 f32/thread) costs 47 regs ->
// occupancy 48.6% -> DRAM only 75.6%. Here pass 1 sums the row WITHOUT keeping
// it (low regs), pass 2 re-reads the row from L2 (guaranteed resident: ~30 MB
// in-flight working set << 126 MB L2), scales, and stores with st.cs so the
// write-once output doesn't evict input rows. DRAM traffic unchanged
// (1 read + 1 write); more warps hide each warp's reduce bubble.

static constexpr int N_ATOM = 1024;                    // floats per row
static constexpr int F4_PER_LANE = N_ATOM / (32 * 4);  // 8

__device__ __forceinline__ void stcs_f4(float4* p, float4 v) {
    asm volatile("st.global.cs.v4.f32 [%0], {%1, %2, %3, %4};"
                 :: "l"(p), "f"(v.x), "f"(v.y), "f"(v.z), "f"(v.w)
                 : "memory");
}

__global__ __launch_bounds__(256) void rownorm2_kernel(
    const float* __restrict__ w,
    float* __restrict__ out,
    int nrows)
{
    int gtid = blockIdx.x * blockDim.x + threadIdx.x;
    int warp = gtid >> 5;
    int lane = threadIdx.x & 31;
    if (warp >= nrows) return;

    const float4* __restrict__ src =
        reinterpret_cast<const float4*>(w + (size_t)warp * N_ATOM);
    float4* __restrict__ dst =
        reinterpret_cast<float4*>(out + (size_t)warp * N_ATOM);

    // Pass 1: stream the row, accumulate partial sum. Values discarded ->
    // only the sum stays live; MLP=8 from the unrolled loads.
    float s = 0.0f;
#pragma unroll
    for (int i = 0; i < F4_PER_LANE; i++) {
        float4 a = src[lane + i * 32];
        s += (a.x + a.y) + (a.z + a.w);
    }

    // Warp tree-reduce.
#pragma unroll
    for (int off = 16; off > 0; off >>= 1)
        s += __shfl_xor_sync(0xFFFFFFFFu, s, off);

    float inv = (s > 0.0f) ? (1.0f / s) : 0.0f;

    // Pass 2: re-read the row (L2 hit), scale, streaming-store.
#pragma unroll
    for (int i = 0; i < F4_PER_LANE; i++) {
        float4 a = src[lane + i * 32];
        a.x *= inv; a.y *= inv; a.z *= inv; a.w *= inv;
        stcs_f4(&dst[lane + i * 32], a);
    }
}

extern "C" void kernel_launch(void* const* d_in, const int* in_sizes, int n_in,
                              void* d_out, int out_size)
{
    const float* w = (const float*)d_in[0];   // edge_weight [K, N*N]
    // d_in[1] = row indices (unused: closed-form e/N), d_in[2] = num_atom
    float* out = (float*)d_out;

    int total = in_sizes[0];                  // K * N * N
    int nrows = total / N_ATOM;               // K * N

    int threads = 256;
    int warps_per_block = threads / 32;
    int blocks = (nrows + warps_per_block - 1) / warps_per_block;
    rownorm2_kernel<<<blocks, threads>>>(w, out, nrows);
}